// round 1
// baseline (speedup 1.0000x reference)
#include <cuda_runtime.h>

// ---------------------------------------------------------------------------
// DiT Swin Transformer block — fp32 baseline.
// B=16, H=W=64, L=4096, C=256, COND=128, HID=1024, NH=8, hd=32, WS=8, SHIFT=4
// ---------------------------------------------------------------------------

namespace {
constexpr int kB     = 16;
constexpr int kH     = 64;
constexpr int kW     = 64;
constexpr int kL     = kH * kW;        // 4096
constexpr int kC     = 256;
constexpr int kCond  = 128;
constexpr int kHid   = 1024;
constexpr int kNH    = 8;
constexpr int kHD    = 32;
constexpr int kWS    = 8;
constexpr int kN     = kWS * kWS;      // 64 tokens / window
constexpr int kShift = 4;
constexpr int kM     = kB * kL;        // 65536 rows
constexpr int kNWin  = kM / kN;        // 1024 windows
}

// ------------------------------- scratch -----------------------------------
__device__ float g_mod1[kB * 2 * kC];
__device__ float g_mod2[kB * 2 * kC];
__device__ float g_h  [(size_t)kM * kC];          //  64 MB
__device__ float g_qkv[(size_t)kM * 3 * kC];      // 201 MB
__device__ float g_ow [(size_t)kM * kC];          //  64 MB
__device__ float g_x2 [(size_t)kM * kC];          //  64 MB
__device__ float g_h2 [(size_t)kM * kC];          //  64 MB
__device__ float g_hid[(size_t)kM * kHid];        // 268 MB

// ------------------------- cond modulation GEMM ----------------------------
// mod = cond @ w + b   : (16,128) @ (128,512) -> (16,512), twice.
__global__ void mod_kernel(const float* __restrict__ cond,
                           const float* __restrict__ w1, const float* __restrict__ b1,
                           const float* __restrict__ w2, const float* __restrict__ b2)
{
    int b     = blockIdx.x;
    int which = blockIdx.y;
    const float* w  = which ? w2 : w1;
    const float* bb = which ? b2 : b1;
    float* out      = which ? g_mod2 : g_mod1;

    __shared__ float cs[kCond];
    int j = threadIdx.x;                    // 0..511
    if (j < kCond) cs[j] = cond[b * kCond + j];
    __syncthreads();

    float s = bb[j];
    #pragma unroll 8
    for (int k = 0; k < kCond; k++) s = fmaf(cs[k], w[k * (2 * kC) + j], s);
    out[b * (2 * kC) + j] = s;
}

// ------------------------------- adaLN -------------------------------------
// out = (g*(1+dg)) * (x-mu)*rsqrt(var+eps) + (beta+db), one row per block.
__global__ void adaln_kernel(const float* __restrict__ x, const float* __restrict__ mod,
                             const float* __restrict__ g,  const float* __restrict__ bt,
                             float* __restrict__ out)
{
    int row = blockIdx.x;
    int c   = threadIdx.x;                  // 0..255
    float v = x[(size_t)row * kC + c];

    __shared__ float sh[8];
    int lane = c & 31, wid = c >> 5;

    float s = v;
    #pragma unroll
    for (int o = 16; o > 0; o >>= 1) s += __shfl_down_sync(0xffffffffu, s, o);
    if (lane == 0) sh[wid] = s;
    __syncthreads();
    if (c == 0) {
        float t = 0.f;
        #pragma unroll
        for (int i = 0; i < 8; i++) t += sh[i];
        sh[0] = t * (1.0f / kC);
    }
    __syncthreads();
    float mu = sh[0];
    __syncthreads();

    float d = v - mu;
    s = d * d;
    #pragma unroll
    for (int o = 16; o > 0; o >>= 1) s += __shfl_down_sync(0xffffffffu, s, o);
    if (lane == 0) sh[wid] = s;
    __syncthreads();
    if (c == 0) {
        float t = 0.f;
        #pragma unroll
        for (int i = 0; i < 8; i++) t += sh[i];
        sh[0] = t * (1.0f / kC);
    }
    __syncthreads();
    float var = sh[0];

    float th = d * rsqrtf(var + 1e-6f);
    int b    = row >> 12;                   // row / 4096
    float dg = mod[b * (2 * kC) + c];
    float db = mod[b * (2 * kC) + kC + c];
    out[(size_t)row * kC + c] = (g[c] * (1.0f + dg)) * th + (bt[c] + db);
}

// ----------------------------- row gathers ---------------------------------
// GATHER 0: identity.
// GATHER 1: window-layout row -> (rolled -SHIFT) h row  (qkv input gather).
// GATHER 2: linear (b,y,x) row -> window-layout o row   (proj input gather,
//           implements reverse-partition + roll +SHIFT).
template <int GATHER>
__device__ __forceinline__ int gather_row(int r)
{
    if (GATHER == 1) {
        int win = r >> 6, n = r & 63;
        int b = win >> 6, wrem = win & 63;
        int yr = ((wrem >> 3) << 3) + (n >> 3);
        int xr = ((wrem & 7) << 3) + (n & 7);
        int y = (yr + kShift) & 63;
        int x = (xr + kShift) & 63;
        return b * kL + y * kW + x;
    } else if (GATHER == 2) {
        int b = r >> 12, rem = r & 4095;
        int y = rem >> 6, x = rem & 63;
        int yr = (y - kShift) & 63;
        int xr = (x - kShift) & 63;
        int win = b * 64 + ((yr >> 3) << 3) + (xr >> 3);
        int n   = ((yr & 7) << 3) + (xr & 7);
        return win * kN + n;
    }
    return r;
}

// ------------------------------ tiled SGEMM --------------------------------
// C[M,N] = gatherA(A)[M,K] @ B[K,N] + bias, optional GELU / residual add.
// BM=BN=64, BK=32, 256 threads, 4x4 per thread.
// EPI: 0 = bias, 1 = bias + exact GELU, 2 = bias + residual add (res, linear).
template <int GATHER, int EPI>
__global__ void gemm_kernel(const float* __restrict__ A, const float* __restrict__ Bw,
                            const float* __restrict__ bias, const float* __restrict__ res,
                            float* __restrict__ C, int K, int N)
{
    __shared__ float As[32][65];   // [k][row], padded: conflict-free stores
    __shared__ float Bs[32][68];   // [k][col], padded

    int tid  = threadIdx.x;        // 0..255
    int tx   = tid & 15, ty = tid >> 4;
    int row0 = blockIdx.x * 64;
    int col0 = blockIdx.y * 64;

    int arow[2];
    #pragma unroll
    for (int it = 0; it < 2; it++) {
        int idx = tid + it * 256;
        arow[it] = gather_row<GATHER>(row0 + (idx >> 3));
    }

    float acc[4][4] = {};

    for (int k0 = 0; k0 < K; k0 += 32) {
        #pragma unroll
        for (int it = 0; it < 2; it++) {
            int idx = tid + it * 256;
            int r = idx >> 3, c4 = idx & 7;
            float4 a = *(const float4*)(A + (size_t)arow[it] * K + k0 + c4 * 4);
            As[c4 * 4 + 0][r] = a.x;
            As[c4 * 4 + 1][r] = a.y;
            As[c4 * 4 + 2][r] = a.z;
            As[c4 * 4 + 3][r] = a.w;
        }
        #pragma unroll
        for (int it = 0; it < 2; it++) {
            int idx = tid + it * 256;
            int r = idx >> 4, c4 = idx & 15;
            *(float4*)&Bs[r][c4 * 4] =
                *(const float4*)(Bw + (size_t)(k0 + r) * N + col0 + c4 * 4);
        }
        __syncthreads();

        #pragma unroll
        for (int kk = 0; kk < 32; kk++) {
            float af[4], bf[4];
            #pragma unroll
            for (int i = 0; i < 4; i++) af[i] = As[kk][ty * 4 + i];
            #pragma unroll
            for (int j = 0; j < 4; j++) bf[j] = Bs[kk][tx * 4 + j];
            #pragma unroll
            for (int i = 0; i < 4; i++)
                #pragma unroll
                for (int j = 0; j < 4; j++)
                    acc[i][j] = fmaf(af[i], bf[j], acc[i][j]);
        }
        __syncthreads();
    }

    #pragma unroll
    for (int i = 0; i < 4; i++) {
        int r = row0 + ty * 4 + i;
        #pragma unroll
        for (int j = 0; j < 4; j++) {
            int cc = col0 + tx * 4 + j;
            float v = acc[i][j] + bias[cc];
            if (EPI == 1) v = 0.5f * v * (1.0f + erff(v * 0.70710678118654752f));
            if (EPI == 2) v += res[(size_t)r * N + cc];
            C[(size_t)r * N + cc] = v;
        }
    }
}

// ------------------------------ attention ----------------------------------
// One block per (window, head). 64 threads, one token row each.
__global__ void attn_kernel(const float* __restrict__ qkv,
                            const float* __restrict__ rpb,
                            float* __restrict__ ow)
{
    __shared__ float ks[kN][kHD + 1];
    __shared__ float vs[kN][kHD + 1];
    __shared__ float ss[kN][kN + 1];

    int win = blockIdx.x, head = blockIdx.y;
    int n = threadIdx.x;                           // 0..63

    size_t base = ((size_t)win * kN + n) * (3 * kC);
    const float* qp = qkv + base + head * kHD;
    const float* kp = qkv + base + kC + head * kHD;
    const float* vp = qkv + base + 2 * kC + head * kHD;

    float q[kHD];
    #pragma unroll
    for (int d = 0; d < kHD; d += 4) {
        float4 t = *(const float4*)(qp + d);
        q[d] = t.x; q[d + 1] = t.y; q[d + 2] = t.z; q[d + 3] = t.w;
        float4 kk = *(const float4*)(kp + d);
        ks[n][d] = kk.x; ks[n][d + 1] = kk.y; ks[n][d + 2] = kk.z; ks[n][d + 3] = kk.w;
        float4 vv = *(const float4*)(vp + d);
        vs[n][d] = vv.x; vs[n][d + 1] = vv.y; vs[n][d + 2] = vv.z; vs[n][d + 3] = vv.w;
    }
    __syncthreads();

    const float scale = 0.17677669529663687f;      // hd^-0.5
    int yi = n >> 3, xi = n & 7;

    float mx = -1e30f;
    for (int j = 0; j < kN; j++) {
        float acc = 0.f;
        #pragma unroll
        for (int d = 0; d < kHD; d++) acc = fmaf(q[d], ks[j][d], acc);
        int idx = (yi - (j >> 3) + 7) * 15 + (xi - (j & 7) + 7);
        acc = fmaf(acc, scale, rpb[idx * kNH + head]);
        ss[n][j] = acc;
        mx = fmaxf(mx, acc);
    }

    float sum = 0.f;
    for (int j = 0; j < kN; j++) {
        float e = expf(ss[n][j] - mx);
        ss[n][j] = e;
        sum += e;
    }
    float inv = 1.0f / sum;

    float o[kHD];
    #pragma unroll
    for (int d = 0; d < kHD; d++) o[d] = 0.f;
    for (int j = 0; j < kN; j++) {
        float e = ss[n][j];
        #pragma unroll
        for (int d = 0; d < kHD; d++) o[d] = fmaf(e, vs[j][d], o[d]);
    }

    float* op = ow + ((size_t)win * kN + n) * kC + head * kHD;
    #pragma unroll
    for (int d = 0; d < kHD; d += 4) {
        float4 t;
        t.x = o[d] * inv; t.y = o[d + 1] * inv;
        t.z = o[d + 2] * inv; t.w = o[d + 3] * inv;
        *(float4*)(op + d) = t;
    }
}

// ------------------------------- launcher ----------------------------------
extern "C" void kernel_launch(void* const* d_in, const int* in_sizes, int n_in,
                              void* d_out, int out_size)
{
    const float* x      = (const float*)d_in[0];
    const float* cond   = (const float*)d_in[1];
    const float* gamma1 = (const float*)d_in[4];
    const float* beta1  = (const float*)d_in[5];
    const float* mod1_w = (const float*)d_in[6];
    const float* mod1_b = (const float*)d_in[7];
    const float* qkv_w  = (const float*)d_in[8];
    const float* qkv_b  = (const float*)d_in[9];
    const float* rpb    = (const float*)d_in[10];
    const float* proj_w = (const float*)d_in[11];
    const float* proj_b = (const float*)d_in[12];
    const float* gamma2 = (const float*)d_in[13];
    const float* beta2  = (const float*)d_in[14];
    const float* mod2_w = (const float*)d_in[15];
    const float* mod2_b = (const float*)d_in[16];
    const float* fc1_w  = (const float*)d_in[17];
    const float* fc1_b  = (const float*)d_in[18];
    const float* fc2_w  = (const float*)d_in[19];
    const float* fc2_b  = (const float*)d_in[20];
    float* out = (float*)d_out;

    void *pv;
    float *p_mod1, *p_mod2, *p_h, *p_qkv, *p_ow, *p_x2, *p_h2, *p_hid;
    cudaGetSymbolAddress(&pv, g_mod1); p_mod1 = (float*)pv;
    cudaGetSymbolAddress(&pv, g_mod2); p_mod2 = (float*)pv;
    cudaGetSymbolAddress(&pv, g_h);    p_h    = (float*)pv;
    cudaGetSymbolAddress(&pv, g_qkv);  p_qkv  = (float*)pv;
    cudaGetSymbolAddress(&pv, g_ow);   p_ow   = (float*)pv;
    cudaGetSymbolAddress(&pv, g_x2);   p_x2   = (float*)pv;
    cudaGetSymbolAddress(&pv, g_h2);   p_h2   = (float*)pv;
    cudaGetSymbolAddress(&pv, g_hid);  p_hid  = (float*)pv;

    // 1. cond modulation vectors (both adaLN blocks)
    mod_kernel<<<dim3(kB, 2), 2 * kC>>>(cond, mod1_w, mod1_b, mod2_w, mod2_b);

    // 2. adaLN #1 -> h
    adaln_kernel<<<kM, kC>>>(x, p_mod1, gamma1, beta1, p_h);

    // 3. qkv GEMM with fused roll(-4)+window-partition gather.
    //    M=65536, K=256, N=768
    gemm_kernel<1, 0><<<dim3(kM / 64, (3 * kC) / 64), 256>>>(
        p_h, qkv_w, qkv_b, nullptr, p_qkv, kC, 3 * kC);

    // 4. windowed attention (1024 windows x 8 heads)
    attn_kernel<<<dim3(kNWin, kNH), kN>>>(p_qkv, rpb, p_ow);

    // 5. proj GEMM with fused reverse-partition + roll(+4) gather + residual.
    //    M=65536, K=256, N=256, x2 = x + o @ proj_w + proj_b
    gemm_kernel<2, 2><<<dim3(kM / 64, kC / 64), 256>>>(
        p_ow, proj_w, proj_b, x, p_x2, kC, kC);

    // 6. adaLN #2 -> h2
    adaln_kernel<<<kM, kC>>>(p_x2, p_mod2, gamma2, beta2, p_h2);

    // 7. fc1 GEMM + exact GELU. M=65536, K=256, N=1024
    gemm_kernel<0, 1><<<dim3(kM / 64, kHid / 64), 256>>>(
        p_h2, fc1_w, fc1_b, nullptr, p_hid, kC, kHid);

    // 8. fc2 GEMM + residual -> out. M=65536, K=1024, N=256
    gemm_kernel<0, 2><<<dim3(kM / 64, kC / 64), 256>>>(
        p_hid, fc2_w, fc2_b, p_x2, out, kHid, kC);
}

// round 4
// speedup vs baseline: 2.4056x; 2.4056x over previous
#include <cuda_runtime.h>
#include <cstdint>

// ---------------------------------------------------------------------------
// DiT Swin Transformer block — tf32 mma.sync GEMMs + online-softmax attention.
// B=16, H=W=64, L=4096, C=256, COND=128, HID=1024, NH=8, hd=32, WS=8, SHIFT=4
// ---------------------------------------------------------------------------

namespace {
constexpr int kB     = 16;
constexpr int kW     = 64;
constexpr int kL     = 64 * 64;        // 4096
constexpr int kC     = 256;
constexpr int kCond  = 128;
constexpr int kHid   = 1024;
constexpr int kNH    = 8;
constexpr int kHD    = 32;
constexpr int kN     = 64;             // tokens / window
constexpr int kShift = 4;
constexpr int kM     = kB * kL;        // 65536 rows
constexpr int kNWin  = kM / kN;        // 1024 windows

constexpr int kBM = 128, kBN = 128, kBK = 32;
constexpr int kAStr = kBK + 4;          // 36 floats  (A smem row stride)
constexpr int kBStr = kBN + 8;          // 136 floats (B smem row stride)
constexpr int kABytes = kBM * kAStr * 4;            // 18432
constexpr int kBBytes = kBK * kBStr * 4;            // 17408
constexpr int kStage  = kABytes + kBBytes;          // 35840
constexpr int kSmemBytes = 2 * kStage;              // 71680
}

// ------------------------------- scratch -----------------------------------
__device__ float g_mod1[kB * 2 * kC];
__device__ float g_mod2[kB * 2 * kC];
__device__ float g_h  [(size_t)kM * kC];
__device__ float g_qkv[(size_t)kM * 3 * kC];
__device__ float g_ow [(size_t)kM * kC];
__device__ float g_x2 [(size_t)kM * kC];
__device__ float g_h2 [(size_t)kM * kC];
__device__ float g_hid[(size_t)kM * kHid];
__device__ float g_wr [786432];                 // tf32-rounded weights

// ---------------------------- helpers ---------------------------------------
__device__ __forceinline__ float rna_tf32(float x) {
    float r;
    asm("cvt.rna.tf32.f32 %0, %1;" : "=f"(r) : "f"(x));
    return r;
}

__device__ __forceinline__ void mma_tf32(float c[4], uint32_t a0, uint32_t a1,
                                         uint32_t a2, uint32_t a3,
                                         uint32_t b0, uint32_t b1) {
    asm volatile(
        "mma.sync.aligned.m16n8k8.row.col.f32.tf32.tf32.f32 "
        "{%0,%1,%2,%3}, {%4,%5,%6,%7}, {%8,%9}, {%0,%1,%2,%3};"
        : "+f"(c[0]), "+f"(c[1]), "+f"(c[2]), "+f"(c[3])
        : "r"(a0), "r"(a1), "r"(a2), "r"(a3), "r"(b0), "r"(b1));
}

// ------------------------- cond modulation GEMM ----------------------------
__global__ void mod_kernel(const float* __restrict__ cond,
                           const float* __restrict__ w1, const float* __restrict__ b1,
                           const float* __restrict__ w2, const float* __restrict__ b2)
{
    int b = blockIdx.x, which = blockIdx.y;
    const float* w  = which ? w2 : w1;
    const float* bb = which ? b2 : b1;
    float* out      = which ? g_mod2 : g_mod1;

    __shared__ float cs[kCond];
    int j = threadIdx.x;
    if (j < kCond) cs[j] = cond[b * kCond + j];
    __syncthreads();

    float s = bb[j];
    #pragma unroll 8
    for (int k = 0; k < kCond; k++) s = fmaf(cs[k], w[k * (2 * kC) + j], s);
    out[b * (2 * kC) + j] = s;
}

// ------------------------------- adaLN -------------------------------------
__global__ void adaln_kernel(const float* __restrict__ x, const float* __restrict__ mod,
                             const float* __restrict__ g,  const float* __restrict__ bt,
                             float* __restrict__ out)
{
    int row = blockIdx.x;
    int c   = threadIdx.x;
    float v = x[(size_t)row * kC + c];

    __shared__ float sh[8];
    int lane = c & 31, wid = c >> 5;

    float s = v;
    #pragma unroll
    for (int o = 16; o > 0; o >>= 1) s += __shfl_down_sync(0xffffffffu, s, o);
    if (lane == 0) sh[wid] = s;
    __syncthreads();
    if (c == 0) {
        float t = 0.f;
        #pragma unroll
        for (int i = 0; i < 8; i++) t += sh[i];
        sh[0] = t * (1.0f / kC);
    }
    __syncthreads();
    float mu = sh[0];
    __syncthreads();

    float d = v - mu;
    s = d * d;
    #pragma unroll
    for (int o = 16; o > 0; o >>= 1) s += __shfl_down_sync(0xffffffffu, s, o);
    if (lane == 0) sh[wid] = s;
    __syncthreads();
    if (c == 0) {
        float t = 0.f;
        #pragma unroll
        for (int i = 0; i < 8; i++) t += sh[i];
        sh[0] = t * (1.0f / kC);
    }
    __syncthreads();
    float var = sh[0];

    float th = d * rsqrtf(var + 1e-6f);
    int b    = row >> 12;
    float dg = mod[b * (2 * kC) + c];
    float db = mod[b * (2 * kC) + kC + c];
    out[(size_t)row * kC + c] = (g[c] * (1.0f + dg)) * th + (bt[c] + db);
}

// --------------------- weight pre-round (tf32 rna copy) --------------------
__global__ void round_copy(const float* __restrict__ src, float* __restrict__ dst, int n)
{
    int i = blockIdx.x * 256 + threadIdx.x;
    if (i < n) dst[i] = rna_tf32(src[i]);
}

// ----------------------------- row gathers ---------------------------------
template <int GATHER>
__device__ __forceinline__ int gather_row(int r)
{
    if (GATHER == 1) {
        int win = r >> 6, n = r & 63;
        int b = win >> 6, wrem = win & 63;
        int yr = ((wrem >> 3) << 3) + (n >> 3);
        int xr = ((wrem & 7) << 3) + (n & 7);
        int y = (yr + kShift) & 63;
        int x = (xr + kShift) & 63;
        return b * kL + y * kW + x;
    } else if (GATHER == 2) {
        int b = r >> 12, rem = r & 4095;
        int y = rem >> 6, x = rem & 63;
        int yr = (y - kShift) & 63;
        int xr = (x - kShift) & 63;
        int win = b * 64 + ((yr >> 3) << 3) + (xr >> 3);
        int n   = ((yr & 7) << 3) + (xr & 7);
        return win * kN + n;
    }
    return r;
}

// --------------------------- tf32 mma GEMM ---------------------------------
// C[M,N] = gatherA(A)[M,K] @ W[K,N] + bias ; EPI: 0 none, 1 GELU, 2 +res.
// 256 threads = 8 warps laid out 4(M) x 2(N); warp tile 32x64.
template <int GATHER, int EPI>
__global__ void __launch_bounds__(256)
gemm_tc(const float* __restrict__ A, const float* __restrict__ Bw,
        const float* __restrict__ bias, const float* __restrict__ res,
        float* __restrict__ C, int K, int N)
{
    extern __shared__ float sm[];

    int tid  = threadIdx.x;
    int wid  = tid >> 5, lane = tid & 31;
    int g    = lane >> 2, t = lane & 3;
    int wm   = wid & 3, wn = wid >> 2;
    int row0 = blockIdx.x * kBM;
    int col0 = blockIdx.y * kBN;

    int arow[4];
    #pragma unroll
    for (int p = 0; p < 4; p++)
        arow[p] = gather_row<GATHER>(row0 + ((p * 256 + tid) >> 3));

    float acc[2][8][4];
    #pragma unroll
    for (int mt = 0; mt < 2; mt++)
        #pragma unroll
        for (int nt = 0; nt < 8; nt++)
            #pragma unroll
            for (int e = 0; e < 4; e++) acc[mt][nt][e] = 0.f;

    float4 ra[4], rb[4];
    int niter = K >> 5;

    // --- global load of tile k0 into registers ---
    auto ldg = [&](int i) {
        int k0 = i << 5;
        #pragma unroll
        for (int p = 0; p < 4; p++) {
            int idx = p * 256 + tid;
            int q = idx & 7;
            ra[p] = *(const float4*)(A + (size_t)arow[p] * K + k0 + q * 4);
        }
        #pragma unroll
        for (int p = 0; p < 4; p++) {
            int idx = p * 256 + tid;
            int r = idx >> 5, c4 = idx & 31;
            rb[p] = *(const float4*)(Bw + (size_t)(k0 + r) * N + col0 + c4 * 4);
        }
    };
    // --- store registers into smem stage s ---
    auto sts = [&](int s) {
        float* As = sm + s * (kStage / 4);
        float* Bs = As + kABytes / 4;
        #pragma unroll
        for (int p = 0; p < 4; p++) {
            int idx = p * 256 + tid;
            int r = idx >> 3, q = idx & 7;
            float4 a = ra[p];
            a.x = rna_tf32(a.x); a.y = rna_tf32(a.y);
            a.z = rna_tf32(a.z); a.w = rna_tf32(a.w);
            *(float4*)(As + r * kAStr + q * 4) = a;
        }
        #pragma unroll
        for (int p = 0; p < 4; p++) {
            int idx = p * 256 + tid;
            int r = idx >> 5, c4 = idx & 31;
            *(float4*)(Bs + r * kBStr + c4 * 4) = rb[p];
        }
    };

    ldg(0);
    sts(0);
    __syncthreads();

    for (int i = 0; i < niter; i++) {
        if (i + 1 < niter) ldg(i + 1);

        const float* As = sm + (i & 1) * (kStage / 4);
        const float* Bs = As + kABytes / 4;

        #pragma unroll
        for (int kk = 0; kk < 4; kk++) {
            uint32_t af[2][4];
            #pragma unroll
            for (int mt = 0; mt < 2; mt++) {
                int m0 = wm * 32 + mt * 16;
                af[mt][0] = __float_as_uint(As[(m0 + g)     * kAStr + kk * 8 + t]);
                af[mt][1] = __float_as_uint(As[(m0 + g + 8) * kAStr + kk * 8 + t]);
                af[mt][2] = __float_as_uint(As[(m0 + g)     * kAStr + kk * 8 + t + 4]);
                af[mt][3] = __float_as_uint(As[(m0 + g + 8) * kAStr + kk * 8 + t + 4]);
            }
            uint32_t bf[8][2];
            #pragma unroll
            for (int nt = 0; nt < 8; nt++) {
                int n0 = wn * 64 + nt * 8;
                bf[nt][0] = __float_as_uint(Bs[(kk * 8 + t)     * kBStr + n0 + g]);
                bf[nt][1] = __float_as_uint(Bs[(kk * 8 + t + 4) * kBStr + n0 + g]);
            }
            #pragma unroll
            for (int mt = 0; mt < 2; mt++)
                #pragma unroll
                for (int nt = 0; nt < 8; nt++)
                    mma_tf32(acc[mt][nt], af[mt][0], af[mt][1], af[mt][2], af[mt][3],
                             bf[nt][0], bf[nt][1]);
        }

        if (i + 1 < niter) {
            __syncthreads();
            sts((i + 1) & 1);
            __syncthreads();
        }
    }

    // ------------------------------ epilogue --------------------------------
    #pragma unroll
    for (int mt = 0; mt < 2; mt++) {
        int r0 = row0 + wm * 32 + mt * 16 + g;
        #pragma unroll
        for (int nt = 0; nt < 8; nt++) {
            int cc = col0 + wn * 64 + nt * 8 + t * 2;
            float2 bv = *(const float2*)(bias + cc);
            float v0 = acc[mt][nt][0] + bv.x;
            float v1 = acc[mt][nt][1] + bv.y;
            float v2 = acc[mt][nt][2] + bv.x;
            float v3 = acc[mt][nt][3] + bv.y;
            if (EPI == 1) {
                v0 = 0.5f * v0 * (1.0f + erff(v0 * 0.70710678118654752f));
                v1 = 0.5f * v1 * (1.0f + erff(v1 * 0.70710678118654752f));
                v2 = 0.5f * v2 * (1.0f + erff(v2 * 0.70710678118654752f));
                v3 = 0.5f * v3 * (1.0f + erff(v3 * 0.70710678118654752f));
            }
            if (EPI == 2) {
                float2 q0 = *(const float2*)(res + (size_t)r0 * N + cc);
                float2 q1 = *(const float2*)(res + (size_t)(r0 + 8) * N + cc);
                v0 += q0.x; v1 += q0.y; v2 += q1.x; v3 += q1.y;
            }
            float2 o0 = {v0, v1}, o1 = {v2, v3};
            *(float2*)(C + (size_t)r0 * N + cc)       = o0;
            *(float2*)(C + (size_t)(r0 + 8) * N + cc) = o1;
        }
    }
}

// ------------------------------ attention ----------------------------------
// One block per (window, head), 64 threads; tiled online softmax.
// K/V smem rows padded to 36 floats (144 B) so float4 row bases stay 16B-aligned.
__global__ void __launch_bounds__(64)
attn_kernel(const float* __restrict__ qkv, const float* __restrict__ rpb,
            float* __restrict__ ow)
{
    __shared__ float ks[kN][kHD + 4];
    __shared__ float vs[kN][kHD + 4];
    __shared__ float btab[225];

    int win = blockIdx.x, head = blockIdx.y;
    int n = threadIdx.x;

    for (int i = n; i < 225; i += 64) btab[i] = rpb[i * kNH + head];

    size_t base = ((size_t)win * kN + n) * (3 * kC);
    const float* qp = qkv + base + head * kHD;
    const float* kp = qp + kC;
    const float* vp = qp + 2 * kC;
    const float scale = 0.17677669529663687f;

    float q[kHD];
    #pragma unroll
    for (int d = 0; d < kHD; d += 4) {
        float4 tq = *(const float4*)(qp + d);
        q[d] = tq.x * scale; q[d + 1] = tq.y * scale;
        q[d + 2] = tq.z * scale; q[d + 3] = tq.w * scale;
        *(float4*)&ks[n][d] = *(const float4*)(kp + d);
        *(float4*)&vs[n][d] = *(const float4*)(vp + d);
    }
    __syncthreads();

    int yi = n >> 3, xi = n & 7;
    float m = -1e30f, sum = 0.f, o[kHD];
    #pragma unroll
    for (int d = 0; d < kHD; d++) o[d] = 0.f;

    #pragma unroll
    for (int jt = 0; jt < 4; jt++) {
        float sc[16];
        float tmax = -1e30f;
        #pragma unroll
        for (int jj = 0; jj < 16; jj++) {
            int j = jt * 16 + jj;
            float acc = 0.f;
            #pragma unroll
            for (int d = 0; d < kHD; d++) acc = fmaf(q[d], ks[j][d], acc);
            acc += btab[(yi - (j >> 3) + 7) * 15 + (xi - (j & 7) + 7)];
            sc[jj] = acc;
            tmax = fmaxf(tmax, acc);
        }
        float mnew = fmaxf(m, tmax);
        float corr = __expf(m - mnew);
        sum *= corr;
        #pragma unroll
        for (int d = 0; d < kHD; d++) o[d] *= corr;
        #pragma unroll
        for (int jj = 0; jj < 16; jj++) {
            int j = jt * 16 + jj;
            float p = __expf(sc[jj] - mnew);
            sum += p;
            #pragma unroll
            for (int d = 0; d < kHD; d++) o[d] = fmaf(p, vs[j][d], o[d]);
        }
        m = mnew;
    }

    float inv = 1.0f / sum;
    float* op = ow + ((size_t)win * kN + n) * kC + head * kHD;
    #pragma unroll
    for (int d = 0; d < kHD; d += 4) {
        float4 tq = {o[d] * inv, o[d + 1] * inv, o[d + 2] * inv, o[d + 3] * inv};
        *(float4*)(op + d) = tq;
    }
}

// ------------------------------- launcher ----------------------------------
extern "C" void kernel_launch(void* const* d_in, const int* in_sizes, int n_in,
                              void* d_out, int out_size)
{
    const float* x      = (const float*)d_in[0];
    const float* cond   = (const float*)d_in[1];
    const float* gamma1 = (const float*)d_in[4];
    const float* beta1  = (const float*)d_in[5];
    const float* mod1_w = (const float*)d_in[6];
    const float* mod1_b = (const float*)d_in[7];
    const float* qkv_w  = (const float*)d_in[8];
    const float* qkv_b  = (const float*)d_in[9];
    const float* rpb    = (const float*)d_in[10];
    const float* proj_w = (const float*)d_in[11];
    const float* proj_b = (const float*)d_in[12];
    const float* gamma2 = (const float*)d_in[13];
    const float* beta2  = (const float*)d_in[14];
    const float* mod2_w = (const float*)d_in[15];
    const float* mod2_b = (const float*)d_in[16];
    const float* fc1_w  = (const float*)d_in[17];
    const float* fc1_b  = (const float*)d_in[18];
    const float* fc2_w  = (const float*)d_in[19];
    const float* fc2_b  = (const float*)d_in[20];
    float* out = (float*)d_out;

    void* pv;
    float *p_mod1, *p_mod2, *p_h, *p_qkv, *p_ow, *p_x2, *p_h2, *p_hid, *p_wr;
    cudaGetSymbolAddress(&pv, g_mod1); p_mod1 = (float*)pv;
    cudaGetSymbolAddress(&pv, g_mod2); p_mod2 = (float*)pv;
    cudaGetSymbolAddress(&pv, g_h);    p_h    = (float*)pv;
    cudaGetSymbolAddress(&pv, g_qkv);  p_qkv  = (float*)pv;
    cudaGetSymbolAddress(&pv, g_ow);   p_ow   = (float*)pv;
    cudaGetSymbolAddress(&pv, g_x2);   p_x2   = (float*)pv;
    cudaGetSymbolAddress(&pv, g_h2);   p_h2   = (float*)pv;
    cudaGetSymbolAddress(&pv, g_hid);  p_hid  = (float*)pv;
    cudaGetSymbolAddress(&pv, g_wr);   p_wr   = (float*)pv;

    float* qkvR = p_wr;                 // [256, 768]
    float* projR = p_wr + 196608;       // [256, 256]
    float* fc1R  = p_wr + 262144;       // [256, 1024]
    float* fc2R  = p_wr + 524288;       // [1024, 256]

    cudaFuncSetAttribute(gemm_tc<1, 0>, cudaFuncAttributeMaxDynamicSharedMemorySize, kSmemBytes);
    cudaFuncSetAttribute(gemm_tc<2, 2>, cudaFuncAttributeMaxDynamicSharedMemorySize, kSmemBytes);
    cudaFuncSetAttribute(gemm_tc<0, 1>, cudaFuncAttributeMaxDynamicSharedMemorySize, kSmemBytes);
    cudaFuncSetAttribute(gemm_tc<0, 2>, cudaFuncAttributeMaxDynamicSharedMemorySize, kSmemBytes);

    // 1. prep: cond modulation + tf32-round weights
    mod_kernel<<<dim3(kB, 2), 2 * kC>>>(cond, mod1_w, mod1_b, mod2_w, mod2_b);
    round_copy<<<768, 256>>>(qkv_w,  qkvR, 196608);
    round_copy<<<256, 256>>>(proj_w, projR, 65536);
    round_copy<<<1024, 256>>>(fc1_w, fc1R, 262144);
    round_copy<<<1024, 256>>>(fc2_w, fc2R, 262144);

    // 2. adaLN #1
    adaln_kernel<<<kM, kC>>>(x, p_mod1, gamma1, beta1, p_h);

    // 3. qkv GEMM (fused roll+partition gather)  M=65536 K=256 N=768
    gemm_tc<1, 0><<<dim3(kM / kBM, 6), 256, kSmemBytes>>>(
        p_h, qkvR, qkv_b, nullptr, p_qkv, kC, 3 * kC);

    // 4. windowed attention
    attn_kernel<<<dim3(kNWin, kNH), kN>>>(p_qkv, rpb, p_ow);

    // 5. proj GEMM (fused reverse gather + residual)  M=65536 K=256 N=256
    gemm_tc<2, 2><<<dim3(kM / kBM, 2), 256, kSmemBytes>>>(
        p_ow, projR, proj_b, x, p_x2, kC, kC);

    // 6. adaLN #2
    adaln_kernel<<<kM, kC>>>(p_x2, p_mod2, gamma2, beta2, p_h2);

    // 7. fc1 GEMM + exact GELU  M=65536 K=256 N=1024
    gemm_tc<0, 1><<<dim3(kM / kBM, 8), 256, kSmemBytes>>>(
        p_h2, fc1R, fc1_b, nullptr, p_hid, kC, kHid);

    // 8. fc2 GEMM + residual -> out  M=65536 K=1024 N=256
    gemm_tc<0, 2><<<dim3(kM / kBM, 2), 256, kSmemBytes>>>(
        p_hid, fc2R, fc2_b, p_x2, out, kHid, kC);
}

// round 5
// speedup vs baseline: 3.4675x; 1.4414x over previous
#include <cuda_runtime.h>
#include <cuda_bf16.h>
#include <cstdint>

// ---------------------------------------------------------------------------
// DiT Swin Transformer block — bf16 mma.sync + ldmatrix GEMMs, fp32 elsewhere.
// B=16, H=W=64, L=4096, C=256, COND=128, HID=1024, NH=8, hd=32, WS=8, SHIFT=4
// ---------------------------------------------------------------------------

namespace {
constexpr int kB     = 16;
constexpr int kW     = 64;
constexpr int kL     = 64 * 64;        // 4096
constexpr int kC     = 256;
constexpr int kCond  = 128;
constexpr int kHid   = 1024;
constexpr int kNH    = 8;
constexpr int kHD    = 32;
constexpr int kN     = 64;             // tokens / window
constexpr int kShift = 4;
constexpr int kM     = kB * kL;        // 65536 rows
constexpr int kNWin  = kM / kN;        // 1024 windows

constexpr int kBM = 128, kBN = 128, kBK = 32;
constexpr int kAStr = kBK + 8;          // 40 bf16 = 80 B rows (16B-multiple)
constexpr int kBStr = kBN + 8;          // 136 bf16 = 272 B rows (16B-multiple)
constexpr int kABytes = kBM * kAStr * 2;            // 10240
constexpr int kBBytes = kBK * kBStr * 2;            // 8704
constexpr int kStage  = kABytes + kBBytes;          // 18944
}

// ------------------------------- scratch -----------------------------------
__device__ float g_mod1[kB * 2 * kC];
__device__ float g_mod2[kB * 2 * kC];
__device__ float g_h  [(size_t)kM * kC];
__device__ float g_qkv[(size_t)kM * 3 * kC];
__device__ float g_ow [(size_t)kM * kC];
__device__ float g_x2 [(size_t)kM * kC];
__device__ float g_h2 [(size_t)kM * kC];
__device__ float g_hid[(size_t)kM * kHid];
__device__ __nv_bfloat16 g_wb[786432];          // bf16 weights

// ---------------------------- helpers ---------------------------------------
__device__ __forceinline__ uint32_t smem_u32(const void* p) {
    uint32_t a;
    asm("{ .reg .u64 t; cvta.to.shared.u64 t, %1; cvt.u32.u64 %0, t; }"
        : "=r"(a) : "l"(p));
    return a;
}
__device__ __forceinline__ void ldsm_x4(uint32_t& r0, uint32_t& r1,
                                        uint32_t& r2, uint32_t& r3, uint32_t a) {
    asm volatile("ldmatrix.sync.aligned.m8n8.x4.shared.b16 {%0,%1,%2,%3}, [%4];"
                 : "=r"(r0), "=r"(r1), "=r"(r2), "=r"(r3) : "r"(a));
}
__device__ __forceinline__ void ldsm_x4_t(uint32_t& r0, uint32_t& r1,
                                          uint32_t& r2, uint32_t& r3, uint32_t a) {
    asm volatile("ldmatrix.sync.aligned.m8n8.x4.trans.shared.b16 {%0,%1,%2,%3}, [%4];"
                 : "=r"(r0), "=r"(r1), "=r"(r2), "=r"(r3) : "r"(a));
}
__device__ __forceinline__ void mma_bf16(float c[4], uint32_t a0, uint32_t a1,
                                         uint32_t a2, uint32_t a3,
                                         uint32_t b0, uint32_t b1) {
    asm volatile(
        "mma.sync.aligned.m16n8k16.row.col.f32.bf16.bf16.f32 "
        "{%0,%1,%2,%3}, {%4,%5,%6,%7}, {%8,%9}, {%0,%1,%2,%3};"
        : "+f"(c[0]), "+f"(c[1]), "+f"(c[2]), "+f"(c[3])
        : "r"(a0), "r"(a1), "r"(a2), "r"(a3), "r"(b0), "r"(b1));
}
__device__ __forceinline__ uint32_t pack_bf16(float x, float y) {
    __nv_bfloat162 v = __floats2bfloat162_rn(x, y);
    return *(uint32_t*)&v;
}

// ------------------------- cond modulation GEMM ----------------------------
__global__ void mod_kernel(const float* __restrict__ cond,
                           const float* __restrict__ w1, const float* __restrict__ b1,
                           const float* __restrict__ w2, const float* __restrict__ b2)
{
    int b = blockIdx.x, which = blockIdx.y;
    const float* w  = which ? w2 : w1;
    const float* bb = which ? b2 : b1;
    float* out      = which ? g_mod2 : g_mod1;

    __shared__ float cs[kCond];
    int j = threadIdx.x;
    if (j < kCond) cs[j] = cond[b * kCond + j];
    __syncthreads();

    float s = bb[j];
    #pragma unroll 8
    for (int k = 0; k < kCond; k++) s = fmaf(cs[k], w[k * (2 * kC) + j], s);
    out[b * (2 * kC) + j] = s;
}

// ------------------------------- adaLN -------------------------------------
__global__ void adaln_kernel(const float* __restrict__ x, const float* __restrict__ mod,
                             const float* __restrict__ g,  const float* __restrict__ bt,
                             float* __restrict__ out)
{
    int row = blockIdx.x;
    int c   = threadIdx.x;
    float v = x[(size_t)row * kC + c];

    __shared__ float sh[8];
    int lane = c & 31, wid = c >> 5;

    float s = v;
    #pragma unroll
    for (int o = 16; o > 0; o >>= 1) s += __shfl_down_sync(0xffffffffu, s, o);
    if (lane == 0) sh[wid] = s;
    __syncthreads();
    if (c == 0) {
        float t = 0.f;
        #pragma unroll
        for (int i = 0; i < 8; i++) t += sh[i];
        sh[0] = t * (1.0f / kC);
    }
    __syncthreads();
    float mu = sh[0];
    __syncthreads();

    float d = v - mu;
    s = d * d;
    #pragma unroll
    for (int o = 16; o > 0; o >>= 1) s += __shfl_down_sync(0xffffffffu, s, o);
    if (lane == 0) sh[wid] = s;
    __syncthreads();
    if (c == 0) {
        float t = 0.f;
        #pragma unroll
        for (int i = 0; i < 8; i++) t += sh[i];
        sh[0] = t * (1.0f / kC);
    }
    __syncthreads();
    float var = sh[0];

    float th = d * rsqrtf(var + 1e-6f);
    int b    = row >> 12;
    float dg = mod[b * (2 * kC) + c];
    float db = mod[b * (2 * kC) + kC + c];
    out[(size_t)row * kC + c] = (g[c] * (1.0f + dg)) * th + (bt[c] + db);
}

// ------------------------ weight fp32 -> bf16 -------------------------------
__global__ void to_bf16(const float* __restrict__ src, __nv_bfloat16* __restrict__ dst,
                        int n)
{
    int i = blockIdx.x * 256 + threadIdx.x;
    if (i < n) dst[i] = __float2bfloat16(src[i]);
}

// ----------------------------- row gathers ---------------------------------
template <int GATHER>
__device__ __forceinline__ int gather_row(int r)
{
    if (GATHER == 1) {
        int win = r >> 6, n = r & 63;
        int b = win >> 6, wrem = win & 63;
        int yr = ((wrem >> 3) << 3) + (n >> 3);
        int xr = ((wrem & 7) << 3) + (n & 7);
        int y = (yr + kShift) & 63;
        int x = (xr + kShift) & 63;
        return b * kL + y * kW + x;
    } else if (GATHER == 2) {
        int b = r >> 12, rem = r & 4095;
        int y = rem >> 6, x = rem & 63;
        int yr = (y - kShift) & 63;
        int xr = (x - kShift) & 63;
        int win = b * 64 + ((yr >> 3) << 3) + (xr >> 3);
        int n   = ((yr & 7) << 3) + (xr & 7);
        return win * kN + n;
    }
    return r;
}

// --------------------------- bf16 mma GEMM ---------------------------------
// C[M,N] = gatherA(A_f32)[M,K] @ W_bf16[K,N] + bias ; EPI: 0 none, 1 GELU, 2 +res.
// 256 threads = 8 warps laid out 4(M) x 2(N); warp tile 32x64.
template <int GATHER, int EPI>
__global__ void __launch_bounds__(256)
gemm_tc(const float* __restrict__ A, const __nv_bfloat16* __restrict__ Bw,
        const float* __restrict__ bias, const float* __restrict__ res,
        float* __restrict__ C, int K, int N)
{
    __shared__ __align__(16) char smem[2 * kStage];

    int tid  = threadIdx.x;
    int wid  = tid >> 5, lane = tid & 31;
    int g    = lane >> 2, t = lane & 3;
    int wm   = wid & 3, wn = wid >> 2;
    int row0 = blockIdx.x * kBM;
    int col0 = blockIdx.y * kBN;

    // ldmatrix lane address components
    int a_r   = (lane & 15);             // A row within 16
    int a_c   = (lane >> 4) << 3;        // A col 0/8 within k16
    int b_r   = (lane & 7) + ((lane >> 3) & 1) * 8;   // B k-row within 16
    int b_c   = (lane >> 4) << 3;        // B n-col 0/8 within 16

    int arow[4];
    #pragma unroll
    for (int p = 0; p < 4; p++)
        arow[p] = gather_row<GATHER>(row0 + ((p * 256 + tid) >> 3));

    float acc[2][8][4];
    #pragma unroll
    for (int mt = 0; mt < 2; mt++)
        #pragma unroll
        for (int nt = 0; nt < 8; nt++)
            #pragma unroll
            for (int e = 0; e < 4; e++) acc[mt][nt][e] = 0.f;

    float4 ra[4];
    uint4  rb[2];
    int niter = K >> 5;

    auto ldg = [&](int i) {
        int k0 = i << 5;
        #pragma unroll
        for (int p = 0; p < 4; p++) {
            int idx = p * 256 + tid;
            int q = idx & 7;
            ra[p] = *(const float4*)(A + (size_t)arow[p] * K + k0 + q * 4);
        }
        #pragma unroll
        for (int p = 0; p < 2; p++) {
            int idx = p * 256 + tid;
            int r = idx >> 4, c8 = idx & 15;
            rb[p] = *(const uint4*)((const char*)Bw +
                     ((size_t)(k0 + r) * N + col0 + c8 * 8) * 2);
        }
    };
    auto sts = [&](int s) {
        char* As = smem + s * kStage;
        char* Bs = As + kABytes;
        #pragma unroll
        for (int p = 0; p < 4; p++) {
            int idx = p * 256 + tid;
            int r = idx >> 3, q = idx & 7;
            uint2 v;
            v.x = pack_bf16(ra[p].x, ra[p].y);
            v.y = pack_bf16(ra[p].z, ra[p].w);
            *(uint2*)(As + r * (kAStr * 2) + q * 8) = v;
        }
        #pragma unroll
        for (int p = 0; p < 2; p++) {
            int idx = p * 256 + tid;
            int r = idx >> 4, c8 = idx & 15;
            *(uint4*)(Bs + r * (kBStr * 2) + c8 * 16) = rb[p];
        }
    };

    ldg(0);
    sts(0);
    __syncthreads();

    for (int i = 0; i < niter; i++) {
        if (i + 1 < niter) ldg(i + 1);

        uint32_t aB = smem_u32(smem + (i & 1) * kStage);
        uint32_t bB = aB + kABytes;

        #pragma unroll
        for (int ks = 0; ks < 2; ks++) {
            int k0 = ks * 16;
            uint32_t af[2][4];
            #pragma unroll
            for (int mt = 0; mt < 2; mt++) {
                uint32_t addr = aB + (wm * 32 + mt * 16 + a_r) * (kAStr * 2)
                                   + (k0 + a_c) * 2;
                ldsm_x4(af[mt][0], af[mt][1], af[mt][2], af[mt][3], addr);
            }
            uint32_t bf[8][2];
            #pragma unroll
            for (int n2 = 0; n2 < 4; n2++) {
                uint32_t addr = bB + (k0 + b_r) * (kBStr * 2)
                                   + (wn * 64 + n2 * 16 + b_c) * 2;
                uint32_t r0, r1, r2, r3;
                ldsm_x4_t(r0, r1, r2, r3, addr);
                bf[n2 * 2 + 0][0] = r0; bf[n2 * 2 + 0][1] = r1;
                bf[n2 * 2 + 1][0] = r2; bf[n2 * 2 + 1][1] = r3;
            }
            #pragma unroll
            for (int mt = 0; mt < 2; mt++)
                #pragma unroll
                for (int nt = 0; nt < 8; nt++)
                    mma_bf16(acc[mt][nt], af[mt][0], af[mt][1], af[mt][2], af[mt][3],
                             bf[nt][0], bf[nt][1]);
        }

        if (i + 1 < niter) {
            __syncthreads();
            sts((i + 1) & 1);
            __syncthreads();
        }
    }

    // ------------------------------ epilogue --------------------------------
    #pragma unroll
    for (int mt = 0; mt < 2; mt++) {
        int r0 = row0 + wm * 32 + mt * 16 + g;
        #pragma unroll
        for (int nt = 0; nt < 8; nt++) {
            int cc = col0 + wn * 64 + nt * 8 + t * 2;
            float2 bv = *(const float2*)(bias + cc);
            float v0 = acc[mt][nt][0] + bv.x;
            float v1 = acc[mt][nt][1] + bv.y;
            float v2 = acc[mt][nt][2] + bv.x;
            float v3 = acc[mt][nt][3] + bv.y;
            if (EPI == 1) {
                v0 = 0.5f * v0 * (1.0f + erff(v0 * 0.70710678118654752f));
                v1 = 0.5f * v1 * (1.0f + erff(v1 * 0.70710678118654752f));
                v2 = 0.5f * v2 * (1.0f + erff(v2 * 0.70710678118654752f));
                v3 = 0.5f * v3 * (1.0f + erff(v3 * 0.70710678118654752f));
            }
            if (EPI == 2) {
                float2 q0 = *(const float2*)(res + (size_t)r0 * N + cc);
                float2 q1 = *(const float2*)(res + (size_t)(r0 + 8) * N + cc);
                v0 += q0.x; v1 += q0.y; v2 += q1.x; v3 += q1.y;
            }
            float2 o0 = {v0, v1}, o1 = {v2, v3};
            *(float2*)(C + (size_t)r0 * N + cc)       = o0;
            *(float2*)(C + (size_t)(r0 + 8) * N + cc) = o1;
        }
    }
}

// ------------------------------ attention ----------------------------------
__global__ void __launch_bounds__(64)
attn_kernel(const float* __restrict__ qkv, const float* __restrict__ rpb,
            float* __restrict__ ow)
{
    __shared__ float ks[kN][kHD + 4];
    __shared__ float vs[kN][kHD + 4];
    __shared__ float btab[225];

    int win = blockIdx.x, head = blockIdx.y;
    int n = threadIdx.x;

    for (int i = n; i < 225; i += 64) btab[i] = rpb[i * kNH + head];

    size_t base = ((size_t)win * kN + n) * (3 * kC);
    const float* qp = qkv + base + head * kHD;
    const float* kp = qp + kC;
    const float* vp = qp + 2 * kC;
    const float scale = 0.17677669529663687f;

    float q[kHD];
    #pragma unroll
    for (int d = 0; d < kHD; d += 4) {
        float4 tq = *(const float4*)(qp + d);
        q[d] = tq.x * scale; q[d + 1] = tq.y * scale;
        q[d + 2] = tq.z * scale; q[d + 3] = tq.w * scale;
        *(float4*)&ks[n][d] = *(const float4*)(kp + d);
        *(float4*)&vs[n][d] = *(const float4*)(vp + d);
    }
    __syncthreads();

    int yi = n >> 3, xi = n & 7;
    float m = -1e30f, sum = 0.f, o[kHD];
    #pragma unroll
    for (int d = 0; d < kHD; d++) o[d] = 0.f;

    #pragma unroll
    for (int jt = 0; jt < 4; jt++) {
        float sc[16];
        float tmax = -1e30f;
        #pragma unroll
        for (int jj = 0; jj < 16; jj++) {
            int j = jt * 16 + jj;
            float acc = 0.f;
            #pragma unroll
            for (int d = 0; d < kHD; d++) acc = fmaf(q[d], ks[j][d], acc);
            acc += btab[(yi - (j >> 3) + 7) * 15 + (xi - (j & 7) + 7)];
            sc[jj] = acc;
            tmax = fmaxf(tmax, acc);
        }
        float mnew = fmaxf(m, tmax);
        float corr = __expf(m - mnew);
        sum *= corr;
        #pragma unroll
        for (int d = 0; d < kHD; d++) o[d] *= corr;
        #pragma unroll
        for (int jj = 0; jj < 16; jj++) {
            int j = jt * 16 + jj;
            float p = __expf(sc[jj] - mnew);
            sum += p;
            #pragma unroll
            for (int d = 0; d < kHD; d++) o[d] = fmaf(p, vs[j][d], o[d]);
        }
        m = mnew;
    }

    float inv = 1.0f / sum;
    float* op = ow + ((size_t)win * kN + n) * kC + head * kHD;
    #pragma unroll
    for (int d = 0; d < kHD; d += 4) {
        float4 tq = {o[d] * inv, o[d + 1] * inv, o[d + 2] * inv, o[d + 3] * inv};
        *(float4*)(op + d) = tq;
    }
}

// ------------------------------- launcher ----------------------------------
extern "C" void kernel_launch(void* const* d_in, const int* in_sizes, int n_in,
                              void* d_out, int out_size)
{
    const float* x      = (const float*)d_in[0];
    const float* cond   = (const float*)d_in[1];
    const float* gamma1 = (const float*)d_in[4];
    const float* beta1  = (const float*)d_in[5];
    const float* mod1_w = (const float*)d_in[6];
    const float* mod1_b = (const float*)d_in[7];
    const float* qkv_w  = (const float*)d_in[8];
    const float* qkv_b  = (const float*)d_in[9];
    const float* rpb    = (const float*)d_in[10];
    const float* proj_w = (const float*)d_in[11];
    const float* proj_b = (const float*)d_in[12];
    const float* gamma2 = (const float*)d_in[13];
    const float* beta2  = (const float*)d_in[14];
    const float* mod2_w = (const float*)d_in[15];
    const float* mod2_b = (const float*)d_in[16];
    const float* fc1_w  = (const float*)d_in[17];
    const float* fc1_b  = (const float*)d_in[18];
    const float* fc2_w  = (const float*)d_in[19];
    const float* fc2_b  = (const float*)d_in[20];
    float* out = (float*)d_out;

    void* pv;
    float *p_mod1, *p_mod2, *p_h, *p_qkv, *p_ow, *p_x2, *p_h2, *p_hid;
    __nv_bfloat16* p_wb;
    cudaGetSymbolAddress(&pv, g_mod1); p_mod1 = (float*)pv;
    cudaGetSymbolAddress(&pv, g_mod2); p_mod2 = (float*)pv;
    cudaGetSymbolAddress(&pv, g_h);    p_h    = (float*)pv;
    cudaGetSymbolAddress(&pv, g_qkv);  p_qkv  = (float*)pv;
    cudaGetSymbolAddress(&pv, g_ow);   p_ow   = (float*)pv;
    cudaGetSymbolAddress(&pv, g_x2);   p_x2   = (float*)pv;
    cudaGetSymbolAddress(&pv, g_h2);   p_h2   = (float*)pv;
    cudaGetSymbolAddress(&pv, g_hid);  p_hid  = (float*)pv;
    cudaGetSymbolAddress(&pv, g_wb);   p_wb   = (__nv_bfloat16*)pv;

    __nv_bfloat16* qkvB  = p_wb;             // [256, 768]
    __nv_bfloat16* projB = p_wb + 196608;    // [256, 256]
    __nv_bfloat16* fc1B  = p_wb + 262144;    // [256, 1024]
    __nv_bfloat16* fc2B  = p_wb + 524288;    // [1024, 256]

    // 1. prep: cond modulation + weight bf16 conversion
    mod_kernel<<<dim3(kB, 2), 2 * kC>>>(cond, mod1_w, mod1_b, mod2_w, mod2_b);
    to_bf16<<<768, 256>>>(qkv_w,  qkvB, 196608);
    to_bf16<<<256, 256>>>(proj_w, projB, 65536);
    to_bf16<<<1024, 256>>>(fc1_w, fc1B, 262144);
    to_bf16<<<1024, 256>>>(fc2_w, fc2B, 262144);

    // 2. adaLN #1
    adaln_kernel<<<kM, kC>>>(x, p_mod1, gamma1, beta1, p_h);

    // 3. qkv GEMM (fused roll+partition gather)  M=65536 K=256 N=768
    gemm_tc<1, 0><<<dim3(kM / kBM, 6), 256>>>(
        p_h, qkvB, qkv_b, nullptr, p_qkv, kC, 3 * kC);

    // 4. windowed attention
    attn_kernel<<<dim3(kNWin, kNH), kN>>>(p_qkv, rpb, p_ow);

    // 5. proj GEMM (fused reverse gather + residual)  M=65536 K=256 N=256
    gemm_tc<2, 2><<<dim3(kM / kBM, 2), 256>>>(
        p_ow, projB, proj_b, x, p_x2, kC, kC);

    // 6. adaLN #2
    adaln_kernel<<<kM, kC>>>(p_x2, p_mod2, gamma2, beta2, p_h2);

    // 7. fc1 GEMM + exact GELU  M=65536 K=256 N=1024
    gemm_tc<0, 1><<<dim3(kM / kBM, 8), 256>>>(
        p_h2, fc1B, fc1_b, nullptr, p_hid, kC, kHid);

    // 8. fc2 GEMM + residual -> out  M=65536 K=1024 N=256
    gemm_tc<0, 2><<<dim3(kM / kBM, 2), 256>>>(
        p_hid, fc2B, fc2_b, p_x2, out, kHid, kC);
}

// round 6
// speedup vs baseline: 4.0180x; 1.1587x over previous
#include <cuda_runtime.h>
#include <cuda_bf16.h>
#include <cstdint>

// ---------------------------------------------------------------------------
// DiT Swin Transformer block — bf16 mma.sync + ldmatrix + cp.async GEMMs.
// bf16 intermediates (zero-cost where consumed by GEMMs), fp32 residual stream.
// B=16, H=W=64, L=4096, C=256, COND=128, HID=1024, NH=8, hd=32, WS=8, SHIFT=4
// ---------------------------------------------------------------------------

namespace {
constexpr int kB     = 16;
constexpr int kW     = 64;
constexpr int kL     = 64 * 64;        // 4096
constexpr int kC     = 256;
constexpr int kCond  = 128;
constexpr int kHid   = 1024;
constexpr int kNH    = 8;
constexpr int kHD    = 32;
constexpr int kN     = 64;             // tokens / window
constexpr int kShift = 4;
constexpr int kM     = kB * kL;        // 65536 rows
constexpr int kNWin  = kM / kN;        // 1024 windows

constexpr int kBM = 128, kBN = 128, kBK = 32;
constexpr int kAStr = kBK + 8;          // 40 bf16 = 80 B rows
constexpr int kBStr = kBN + 8;          // 136 bf16 = 272 B rows
constexpr int kABytes = kBM * kAStr * 2;            // 10240
constexpr int kBBytes = kBK * kBStr * 2;            // 8704
constexpr int kStage  = kABytes + kBBytes;          // 18944
constexpr int kStages = 3;
}

// ------------------------------- scratch -----------------------------------
__device__ float g_mod1[kB * 2 * kC];
__device__ float g_mod2[kB * 2 * kC];
__device__ __align__(16) __nv_bfloat16 g_h  [(size_t)kM * kC];
__device__ __align__(16) __nv_bfloat16 g_qkv[(size_t)kM * 3 * kC];
__device__ __align__(16) __nv_bfloat16 g_ow [(size_t)kM * kC];
__device__ __align__(16) float         g_x2 [(size_t)kM * kC];
__device__ __align__(16) __nv_bfloat16 g_h2 [(size_t)kM * kC];
__device__ __align__(16) __nv_bfloat16 g_hid[(size_t)kM * kHid];
__device__ __align__(16) __nv_bfloat16 g_wb[786432];          // bf16 weights

// ---------------------------- helpers ---------------------------------------
__device__ __forceinline__ uint32_t smem_u32(const void* p) {
    uint32_t a;
    asm("{ .reg .u64 t; cvta.to.shared.u64 t, %1; cvt.u32.u64 %0, t; }"
        : "=r"(a) : "l"(p));
    return a;
}
__device__ __forceinline__ void ldsm_x4(uint32_t& r0, uint32_t& r1,
                                        uint32_t& r2, uint32_t& r3, uint32_t a) {
    asm volatile("ldmatrix.sync.aligned.m8n8.x4.shared.b16 {%0,%1,%2,%3}, [%4];"
                 : "=r"(r0), "=r"(r1), "=r"(r2), "=r"(r3) : "r"(a));
}
__device__ __forceinline__ void ldsm_x4_t(uint32_t& r0, uint32_t& r1,
                                          uint32_t& r2, uint32_t& r3, uint32_t a) {
    asm volatile("ldmatrix.sync.aligned.m8n8.x4.trans.shared.b16 {%0,%1,%2,%3}, [%4];"
                 : "=r"(r0), "=r"(r1), "=r"(r2), "=r"(r3) : "r"(a));
}
__device__ __forceinline__ void mma_bf16(float c[4], uint32_t a0, uint32_t a1,
                                         uint32_t a2, uint32_t a3,
                                         uint32_t b0, uint32_t b1) {
    asm volatile(
        "mma.sync.aligned.m16n8k16.row.col.f32.bf16.bf16.f32 "
        "{%0,%1,%2,%3}, {%4,%5,%6,%7}, {%8,%9}, {%0,%1,%2,%3};"
        : "+f"(c[0]), "+f"(c[1]), "+f"(c[2]), "+f"(c[3])
        : "r"(a0), "r"(a1), "r"(a2), "r"(a3), "r"(b0), "r"(b1));
}
__device__ __forceinline__ uint32_t pack_bf16(float x, float y) {
    __nv_bfloat162 v = __floats2bfloat162_rn(x, y);
    return *(uint32_t*)&v;
}
__device__ __forceinline__ void store2(float* C, size_t off, float a, float b) {
    float2 v = {a, b};
    *(float2*)(C + off) = v;
}
__device__ __forceinline__ void store2(__nv_bfloat16* C, size_t off, float a, float b) {
    *(uint32_t*)(C + off) = pack_bf16(a, b);
}

#define CP16(dst, src) \
    asm volatile("cp.async.cg.shared.global [%0], [%1], 16;" :: "r"(dst), "l"(src))
#define CP_COMMIT() asm volatile("cp.async.commit_group;")
#define CP_WAIT2()  asm volatile("cp.async.wait_group 2;")

// ------------------------- cond modulation GEMM ----------------------------
__global__ void mod_kernel(const float* __restrict__ cond,
                           const float* __restrict__ w1, const float* __restrict__ b1,
                           const float* __restrict__ w2, const float* __restrict__ b2)
{
    int b = blockIdx.x, which = blockIdx.y;
    const float* w  = which ? w2 : w1;
    const float* bb = which ? b2 : b1;
    float* out      = which ? g_mod2 : g_mod1;

    __shared__ float cs[kCond];
    int j = threadIdx.x;
    if (j < kCond) cs[j] = cond[b * kCond + j];
    __syncthreads();

    float s = bb[j];
    #pragma unroll 8
    for (int k = 0; k < kCond; k++) s = fmaf(cs[k], w[k * (2 * kC) + j], s);
    out[b * (2 * kC) + j] = s;
}

// ------------------------------- adaLN (fp32 in, bf16 out) -----------------
__global__ void adaln_kernel(const float* __restrict__ x, const float* __restrict__ mod,
                             const float* __restrict__ g,  const float* __restrict__ bt,
                             __nv_bfloat16* __restrict__ out)
{
    int row = blockIdx.x;
    int c   = threadIdx.x;
    float v = x[(size_t)row * kC + c];

    __shared__ float sh[8];
    int lane = c & 31, wid = c >> 5;

    float s = v;
    #pragma unroll
    for (int o = 16; o > 0; o >>= 1) s += __shfl_down_sync(0xffffffffu, s, o);
    if (lane == 0) sh[wid] = s;
    __syncthreads();
    if (c == 0) {
        float t = 0.f;
        #pragma unroll
        for (int i = 0; i < 8; i++) t += sh[i];
        sh[0] = t * (1.0f / kC);
    }
    __syncthreads();
    float mu = sh[0];
    __syncthreads();

    float d = v - mu;
    s = d * d;
    #pragma unroll
    for (int o = 16; o > 0; o >>= 1) s += __shfl_down_sync(0xffffffffu, s, o);
    if (lane == 0) sh[wid] = s;
    __syncthreads();
    if (c == 0) {
        float t = 0.f;
        #pragma unroll
        for (int i = 0; i < 8; i++) t += sh[i];
        sh[0] = t * (1.0f / kC);
    }
    __syncthreads();
    float var = sh[0];

    float th = d * rsqrtf(var + 1e-6f);
    int b    = row >> 12;
    float dg = mod[b * (2 * kC) + c];
    float db = mod[b * (2 * kC) + kC + c];
    out[(size_t)row * kC + c] =
        __float2bfloat16((g[c] * (1.0f + dg)) * th + (bt[c] + db));
}

// ------------------------ weight fp32 -> bf16 -------------------------------
__global__ void to_bf16(const float* __restrict__ src, __nv_bfloat16* __restrict__ dst,
                        int n)
{
    int i = blockIdx.x * 256 + threadIdx.x;
    if (i < n) dst[i] = __float2bfloat16(src[i]);
}

// ----------------------------- row gathers ---------------------------------
template <int GATHER>
__device__ __forceinline__ int gather_row(int r)
{
    if (GATHER == 1) {
        int win = r >> 6, n = r & 63;
        int b = win >> 6, wrem = win & 63;
        int yr = ((wrem >> 3) << 3) + (n >> 3);
        int xr = ((wrem & 7) << 3) + (n & 7);
        int y = (yr + kShift) & 63;
        int x = (xr + kShift) & 63;
        return b * kL + y * kW + x;
    } else if (GATHER == 2) {
        int b = r >> 12, rem = r & 4095;
        int y = rem >> 6, x = rem & 63;
        int yr = (y - kShift) & 63;
        int xr = (x - kShift) & 63;
        int win = b * 64 + ((yr >> 3) << 3) + (xr >> 3);
        int n   = ((yr & 7) << 3) + (xr & 7);
        return win * kN + n;
    }
    return r;
}

// --------------------------- bf16 mma GEMM (cp.async x3) -------------------
// C[M,N] = gatherA(A_bf16)[M,K] @ W_bf16[K,N] + bias ; EPI: 0 none, 1 GELU, 2 +res.
template <int GATHER, int EPI, typename OutT>
__global__ void __launch_bounds__(256)
gemm_tc(const __nv_bfloat16* __restrict__ A, const __nv_bfloat16* __restrict__ Bw,
        const float* __restrict__ bias, const float* __restrict__ res,
        OutT* __restrict__ C, int K, int N)
{
    __shared__ __align__(128) char smem[kStages * kStage];

    int tid  = threadIdx.x;
    int wid  = tid >> 5, lane = tid & 31;
    int g    = lane >> 2, t = lane & 3;
    int wm   = wid & 3, wn = wid >> 2;
    int row0 = blockIdx.x * kBM;
    int col0 = blockIdx.y * kBN;

    // ldmatrix lane address components
    int a_r = (lane & 15);
    int a_c = (lane >> 4) << 3;
    int b_r = (lane & 7) + ((lane >> 3) & 1) * 8;
    int b_c = (lane >> 4) << 3;

    // cp.async A rows for this thread (2 chunks: idx=tid, tid+256; row=idx>>2)
    int arowA[2];
    arowA[0] = gather_row<GATHER>(row0 + (tid >> 2));
    arowA[1] = gather_row<GATHER>(row0 + (tid >> 2) + 64);

    float acc[2][8][4];
    #pragma unroll
    for (int mt = 0; mt < 2; mt++)
        #pragma unroll
        for (int nt = 0; nt < 8; nt++)
            #pragma unroll
            for (int e = 0; e < 4; e++) acc[mt][nt][e] = 0.f;

    int niter = K >> 5;

    auto load_stage = [&](int i, int slot) {
        int k0 = i << 5;
        char* As = smem + slot * kStage;
        char* Bs = As + kABytes;
        #pragma unroll
        for (int p = 0; p < 2; p++) {
            int idx = tid + p * 256;
            int r = idx >> 2, ch = idx & 3;
            uint32_t dst = smem_u32(As + r * (kAStr * 2) + ch * 16);
            CP16(dst, A + (size_t)arowA[p] * K + k0 + ch * 8);
        }
        #pragma unroll
        for (int p = 0; p < 2; p++) {
            int idx = tid + p * 256;
            int r = idx >> 4, ch = idx & 15;
            uint32_t dst = smem_u32(Bs + r * (kBStr * 2) + ch * 16);
            CP16(dst, Bw + (size_t)(k0 + r) * N + col0 + ch * 8);
        }
        CP_COMMIT();
    };

    #pragma unroll
    for (int s = 0; s < kStages; s++) load_stage(s, s);

    for (int i = 0; i < niter; i++) {
        CP_WAIT2();
        __syncthreads();

        int slot = i % 3;
        uint32_t aB = smem_u32(smem + slot * kStage);
        uint32_t bB = aB + kABytes;

        #pragma unroll
        for (int ks = 0; ks < 2; ks++) {
            int k0 = ks * 16;
            uint32_t af[2][4];
            #pragma unroll
            for (int mt = 0; mt < 2; mt++) {
                uint32_t addr = aB + (wm * 32 + mt * 16 + a_r) * (kAStr * 2)
                                   + (k0 + a_c) * 2;
                ldsm_x4(af[mt][0], af[mt][1], af[mt][2], af[mt][3], addr);
            }
            uint32_t bf[8][2];
            #pragma unroll
            for (int n2 = 0; n2 < 4; n2++) {
                uint32_t addr = bB + (k0 + b_r) * (kBStr * 2)
                                   + (wn * 64 + n2 * 16 + b_c) * 2;
                uint32_t r0, r1, r2, r3;
                ldsm_x4_t(r0, r1, r2, r3, addr);
                bf[n2 * 2 + 0][0] = r0; bf[n2 * 2 + 0][1] = r1;
                bf[n2 * 2 + 1][0] = r2; bf[n2 * 2 + 1][1] = r3;
            }
            #pragma unroll
            for (int mt = 0; mt < 2; mt++)
                #pragma unroll
                for (int nt = 0; nt < 8; nt++)
                    mma_bf16(acc[mt][nt], af[mt][0], af[mt][1], af[mt][2], af[mt][3],
                             bf[nt][0], bf[nt][1]);
        }
        __syncthreads();

        if (i + 3 < niter) load_stage(i + 3, slot);
        else CP_COMMIT();                       // keep group count uniform
    }

    // ------------------------------ epilogue --------------------------------
    #pragma unroll
    for (int mt = 0; mt < 2; mt++) {
        int r0 = row0 + wm * 32 + mt * 16 + g;
        #pragma unroll
        for (int nt = 0; nt < 8; nt++) {
            int cc = col0 + wn * 64 + nt * 8 + t * 2;
            float2 bv = *(const float2*)(bias + cc);
            float v0 = acc[mt][nt][0] + bv.x;
            float v1 = acc[mt][nt][1] + bv.y;
            float v2 = acc[mt][nt][2] + bv.x;
            float v3 = acc[mt][nt][3] + bv.y;
            if (EPI == 1) {
                v0 = 0.5f * v0 * (1.0f + erff(v0 * 0.70710678118654752f));
                v1 = 0.5f * v1 * (1.0f + erff(v1 * 0.70710678118654752f));
                v2 = 0.5f * v2 * (1.0f + erff(v2 * 0.70710678118654752f));
                v3 = 0.5f * v3 * (1.0f + erff(v3 * 0.70710678118654752f));
            }
            if (EPI == 2) {
                float2 q0 = *(const float2*)(res + (size_t)r0 * N + cc);
                float2 q1 = *(const float2*)(res + (size_t)(r0 + 8) * N + cc);
                v0 += q0.x; v1 += q0.y; v2 += q1.x; v3 += q1.y;
            }
            store2(C, (size_t)r0 * N + cc, v0, v1);
            store2(C, (size_t)(r0 + 8) * N + cc, v2, v3);
        }
    }
}

// ------------------------------ attention ----------------------------------
// bf16 q/k/v in, fp32 math, bf16 out. float4 smem broadcasts in the hot loops.
__global__ void __launch_bounds__(64)
attn_kernel(const __nv_bfloat16* __restrict__ qkv, const float* __restrict__ rpb,
            __nv_bfloat16* __restrict__ ow)
{
    __shared__ float ks[kN][kHD + 4];
    __shared__ float vs[kN][kHD + 4];
    __shared__ float btab[225];

    int win = blockIdx.x, head = blockIdx.y;
    int n = threadIdx.x;

    for (int i = n; i < 225; i += 64) btab[i] = rpb[i * kNH + head];

    size_t base = ((size_t)win * kN + n) * (3 * kC);
    const __nv_bfloat16* qp = qkv + base + head * kHD;
    const __nv_bfloat16* kp = qp + kC;
    const __nv_bfloat16* vp = qp + 2 * kC;
    const float scale = 0.17677669529663687f;

    float q[kHD];
    #pragma unroll
    for (int d = 0; d < kHD; d += 8) {
        uint4 tq = *(const uint4*)(qp + d);
        uint4 tk = *(const uint4*)(kp + d);
        uint4 tv = *(const uint4*)(vp + d);
        const __nv_bfloat162* q2 = (const __nv_bfloat162*)&tq;
        const __nv_bfloat162* k2 = (const __nv_bfloat162*)&tk;
        const __nv_bfloat162* v2 = (const __nv_bfloat162*)&tv;
        #pragma unroll
        for (int e = 0; e < 4; e++) {
            float2 fq = __bfloat1622float2(q2[e]);
            float2 fk = __bfloat1622float2(k2[e]);
            float2 fv = __bfloat1622float2(v2[e]);
            q[d + 2 * e]     = fq.x * scale;
            q[d + 2 * e + 1] = fq.y * scale;
            ks[n][d + 2 * e] = fk.x; ks[n][d + 2 * e + 1] = fk.y;
            vs[n][d + 2 * e] = fv.x; vs[n][d + 2 * e + 1] = fv.y;
        }
    }
    __syncthreads();

    int yi = n >> 3, xi = n & 7;
    float m = -1e30f, sum = 0.f, o[kHD];
    #pragma unroll
    for (int d = 0; d < kHD; d++) o[d] = 0.f;

    #pragma unroll
    for (int jt = 0; jt < 4; jt++) {
        float sc[16];
        float tmax = -1e30f;
        #pragma unroll
        for (int jj = 0; jj < 16; jj++) {
            int j = jt * 16 + jj;
            float acc = 0.f;
            #pragma unroll
            for (int d4 = 0; d4 < kHD; d4 += 4) {
                float4 kv = *(const float4*)&ks[j][d4];
                acc = fmaf(q[d4],     kv.x, acc);
                acc = fmaf(q[d4 + 1], kv.y, acc);
                acc = fmaf(q[d4 + 2], kv.z, acc);
                acc = fmaf(q[d4 + 3], kv.w, acc);
            }
            acc += btab[(yi - (j >> 3) + 7) * 15 + (xi - (j & 7) + 7)];
            sc[jj] = acc;
            tmax = fmaxf(tmax, acc);
        }
        float mnew = fmaxf(m, tmax);
        float corr = __expf(m - mnew);
        sum *= corr;
        #pragma unroll
        for (int d = 0; d < kHD; d++) o[d] *= corr;
        #pragma unroll
        for (int jj = 0; jj < 16; jj++) {
            int j = jt * 16 + jj;
            float p = __expf(sc[jj] - mnew);
            sum += p;
            #pragma unroll
            for (int d4 = 0; d4 < kHD; d4 += 4) {
                float4 vv = *(const float4*)&vs[j][d4];
                o[d4]     = fmaf(p, vv.x, o[d4]);
                o[d4 + 1] = fmaf(p, vv.y, o[d4 + 1]);
                o[d4 + 2] = fmaf(p, vv.z, o[d4 + 2]);
                o[d4 + 3] = fmaf(p, vv.w, o[d4 + 3]);
            }
        }
        m = mnew;
    }

    float inv = 1.0f / sum;
    __nv_bfloat16* op = ow + ((size_t)win * kN + n) * kC + head * kHD;
    #pragma unroll
    for (int d = 0; d < kHD; d += 8) {
        uint4 pk;
        pk.x = pack_bf16(o[d]     * inv, o[d + 1] * inv);
        pk.y = pack_bf16(o[d + 2] * inv, o[d + 3] * inv);
        pk.z = pack_bf16(o[d + 4] * inv, o[d + 5] * inv);
        pk.w = pack_bf16(o[d + 6] * inv, o[d + 7] * inv);
        *(uint4*)(op + d) = pk;
    }
}

// ------------------------------- launcher ----------------------------------
extern "C" void kernel_launch(void* const* d_in, const int* in_sizes, int n_in,
                              void* d_out, int out_size)
{
    const float* x      = (const float*)d_in[0];
    const float* cond   = (const float*)d_in[1];
    const float* gamma1 = (const float*)d_in[4];
    const float* beta1  = (const float*)d_in[5];
    const float* mod1_w = (const float*)d_in[6];
    const float* mod1_b = (const float*)d_in[7];
    const float* qkv_w  = (const float*)d_in[8];
    const float* qkv_b  = (const float*)d_in[9];
    const float* rpb    = (const float*)d_in[10];
    const float* proj_w = (const float*)d_in[11];
    const float* proj_b = (const float*)d_in[12];
    const float* gamma2 = (const float*)d_in[13];
    const float* beta2  = (const float*)d_in[14];
    const float* mod2_w = (const float*)d_in[15];
    const float* mod2_b = (const float*)d_in[16];
    const float* fc1_w  = (const float*)d_in[17];
    const float* fc1_b  = (const float*)d_in[18];
    const float* fc2_w  = (const float*)d_in[19];
    const float* fc2_b  = (const float*)d_in[20];
    float* out = (float*)d_out;

    void* pv;
    float *p_mod1, *p_mod2, *p_x2;
    __nv_bfloat16 *p_h, *p_qkv, *p_ow, *p_h2, *p_hid, *p_wb;
    cudaGetSymbolAddress(&pv, g_mod1); p_mod1 = (float*)pv;
    cudaGetSymbolAddress(&pv, g_mod2); p_mod2 = (float*)pv;
    cudaGetSymbolAddress(&pv, g_h);    p_h    = (__nv_bfloat16*)pv;
    cudaGetSymbolAddress(&pv, g_qkv);  p_qkv  = (__nv_bfloat16*)pv;
    cudaGetSymbolAddress(&pv, g_ow);   p_ow   = (__nv_bfloat16*)pv;
    cudaGetSymbolAddress(&pv, g_x2);   p_x2   = (float*)pv;
    cudaGetSymbolAddress(&pv, g_h2);   p_h2   = (__nv_bfloat16*)pv;
    cudaGetSymbolAddress(&pv, g_hid);  p_hid  = (__nv_bfloat16*)pv;
    cudaGetSymbolAddress(&pv, g_wb);   p_wb   = (__nv_bfloat16*)pv;

    __nv_bfloat16* qkvB  = p_wb;             // [256, 768]
    __nv_bfloat16* projB = p_wb + 196608;    // [256, 256]
    __nv_bfloat16* fc1B  = p_wb + 262144;    // [256, 1024]
    __nv_bfloat16* fc2B  = p_wb + 524288;    // [1024, 256]

    // 1. prep: cond modulation + weight bf16 conversion
    mod_kernel<<<dim3(kB, 2), 2 * kC>>>(cond, mod1_w, mod1_b, mod2_w, mod2_b);
    to_bf16<<<768, 256>>>(qkv_w,  qkvB, 196608);
    to_bf16<<<256, 256>>>(proj_w, projB, 65536);
    to_bf16<<<1024, 256>>>(fc1_w, fc1B, 262144);
    to_bf16<<<1024, 256>>>(fc2_w, fc2B, 262144);

    // 2. adaLN #1 (fp32 -> bf16)
    adaln_kernel<<<kM, kC>>>(x, p_mod1, gamma1, beta1, p_h);

    // 3. qkv GEMM (fused roll+partition gather)  M=65536 K=256 N=768 -> bf16
    gemm_tc<1, 0, __nv_bfloat16><<<dim3(kM / kBM, 6), 256>>>(
        p_h, qkvB, qkv_b, nullptr, p_qkv, kC, 3 * kC);

    // 4. windowed attention (bf16 in/out)
    attn_kernel<<<dim3(kNWin, kNH), kN>>>(p_qkv, rpb, p_ow);

    // 5. proj GEMM (fused reverse gather + residual)  -> fp32 x2
    gemm_tc<2, 2, float><<<dim3(kM / kBM, 2), 256>>>(
        p_ow, projB, proj_b, x, p_x2, kC, kC);

    // 6. adaLN #2 (fp32 -> bf16)
    adaln_kernel<<<kM, kC>>>(p_x2, p_mod2, gamma2, beta2, p_h2);

    // 7. fc1 GEMM + exact GELU  -> bf16 hid
    gemm_tc<0, 1, __nv_bfloat16><<<dim3(kM / kBM, 8), 256>>>(
        p_h2, fc1B, fc1_b, nullptr, p_hid, kC, kHid);

    // 8. fc2 GEMM + residual -> fp32 out
    gemm_tc<0, 2, float><<<dim3(kM / kBM, 2), 256>>>(
        p_hid, fc2B, fc2_b, p_x2, out, kHid, kC);
}